// round 2
// baseline (speedup 1.0000x reference)
#include <cuda_runtime.h>
#include <math.h>

#define C 512
#define KSEL 256
#define HW 25600
#define HH 160
#define WW 160
#define EPS 1e-5f

// ---------------- device scratch ----------------
__device__ float g_avg[C];
__device__ float g_max[C];
__device__ float g_scales[C];
__device__ int   g_idx[KSEL];
__device__ int   g_pos[C];
__device__ float g_weffT[768 * C];        // [k][co], k in 0..767
__device__ float g_w2t[C * 9 * C];        // [(ci*9+t)][co]
__device__ float g_x2[KSEL * HW];         // depthwise output
__device__ float g_h[C * HW];             // after 1x1 conv + bn2

// ---------------- kernel 1: per-channel avg + max ----------------
__global__ void reduce_kernel(const float* __restrict__ x) {
    int c = blockIdx.x;
    const float* xc = x + (size_t)c * HW;
    float s = 0.f, m = -1e30f;
    for (int i = threadIdx.x; i < HW; i += blockDim.x) {
        float v = xc[i];
        s += v;
        m = fmaxf(m, v);
    }
    for (int o = 16; o > 0; o >>= 1) {
        s += __shfl_xor_sync(0xffffffffu, s, o);
        m = fmaxf(m, __shfl_xor_sync(0xffffffffu, m, o));
    }
    __shared__ float ws[8], wm[8];
    int wid = threadIdx.x >> 5;
    if ((threadIdx.x & 31) == 0) { ws[wid] = s; wm[wid] = m; }
    __syncthreads();
    if (threadIdx.x == 0) {
        float st = 0.f, mt = -1e30f;
        for (int i = 0; i < 8; i++) { st += ws[i]; mt = fmaxf(mt, wm[i]); }
        g_avg[c] = st / 25600.f;
        g_max[c] = mt;
    }
}

// ---------------- kernel 2: MLP + sigmoid + top-K selection ----------------
__global__ void mlp_select_kernel(const float* __restrict__ wfc1,
                                  const float* __restrict__ wfc2) {
    __shared__ float s_avg[C], s_max[C], s_hid[C], s_sc[C];
    __shared__ int s_sel[C];
    int t = threadIdx.x;
    s_avg[t] = g_avg[t];
    s_max[t] = g_max[t];
    __syncthreads();
    // hidden layers: threads 0..255 -> hid(avg), 256..511 -> hid(max)
    {
        const float* src = (t < 256) ? s_avg : s_max;
        int k = t & 255;
        const float* wr = wfc1 + (size_t)k * C;
        float acc = 0.f;
        #pragma unroll 8
        for (int c = 0; c < C; c++) acc += src[c] * wr[c];
        s_hid[t] = fmaxf(acc, 0.f);
    }
    __syncthreads();
    float acc = 0.f;
    {
        const float* wr = wfc2 + (size_t)t * 256;
        #pragma unroll 8
        for (int k = 0; k < 256; k++) acc += (s_hid[k] + s_hid[256 + k]) * wr[k];
    }
    float sc = 1.f / (1.f + expf(-acc));
    s_sc[t] = sc;
    g_scales[t] = sc;
    __syncthreads();
    // rank = number of elements that beat me (tie -> lower index wins)
    int rank = 0;
    for (int j = 0; j < C; j++) {
        float sj = s_sc[j];
        rank += (sj > sc) || (sj == sc && j < t);
    }
    int sel = (rank < KSEL) ? 1 : 0;
    s_sel[t] = sel;
    __syncthreads();
    int pos = 0;
    for (int j = 0; j < t; j++) pos += s_sel[j];
    if (sel) { g_idx[pos] = t; g_pos[t] = pos; }
    else      g_pos[t] = -1;
}

// ---------------- kernel 3: build effective 1x1 weights (transposed [k][co]) ----------------
__global__ void weff_kernel(const float* __restrict__ w_dc1) {
    int e = blockIdx.x * blockDim.x + threadIdx.x;   // 768*512
    if (e >= 768 * C) return;
    int k = e >> 9;
    int co = e & 511;
    float v;
    if (k < C) {
        v = g_scales[k] * w_dc1[(size_t)co * 1024 + k];
        int p = g_pos[k];
        if (p >= 0) v += w_dc1[(size_t)co * 1024 + 512 + p];
    } else {
        v = w_dc1[(size_t)co * 1024 + 768 + (k - C)];
    }
    g_weffT[(size_t)k * C + co] = v;
}

// ---------------- kernel 4: transpose w_dc2 -> [(ci*9+t)][co] ----------------
__global__ void w2t_kernel(const float* __restrict__ w_dc2) {
    int e = blockIdx.x * blockDim.x + threadIdx.x;   // 512*9*512
    if (e >= C * 9 * C) return;
    int co = e & 511;
    int kt = e >> 9;
    int ci = kt / 9;
    int tp = kt - ci * 9;
    g_w2t[e] = w_dc2[(size_t)co * (C * 9) + ci * 9 + tp];
}

// ---------------- kernel 5: depthwise 3x3 + bn1 + relu on selected channels ----------------
__global__ void x2_kernel(const float* __restrict__ x,
                          const float* __restrict__ wch,
                          const float* __restrict__ g1, const float* __restrict__ b1,
                          const float* __restrict__ m1, const float* __restrict__ v1) {
    int j = blockIdx.x;
    int ch = g_idx[j];
    float s = g1[j] * rsqrtf(v1[j] + EPS);
    float sh = b1[j] - m1[j] * s;
    float w[9];
    #pragma unroll
    for (int t = 0; t < 9; t++) w[t] = wch[j * 9 + t];
    const float* xc = x + (size_t)ch * HW;
    float* oc = g_x2 + (size_t)j * HW;
    int pbase = blockIdx.y * 1024;
    for (int p = pbase + threadIdx.x; p < pbase + 1024; p += 256) {
        int y = p / WW, xx = p - y * WW;
        float acc = 0.f;
        #pragma unroll
        for (int dy = 0; dy < 3; dy++) {
            int gy = y + dy - 1;
            if (gy < 0 || gy >= HH) continue;
            #pragma unroll
            for (int dx = 0; dx < 3; dx++) {
                int gx = xx + dx - 1;
                if (gx < 0 || gx >= WW) continue;
                acc += xc[gy * WW + gx] * w[dy * 3 + dx];
            }
        }
        oc[p] = fmaxf(acc * s + sh, 0.f);
    }
}

// ---------------- kernel 6: fused concat-1x1-conv GEMM (M=512, N=25600, K=768) + bn2 ----------------
__global__ __launch_bounds__(256) void gemm_h_kernel(
        const float* __restrict__ x,
        const float* __restrict__ bdc1,
        const float* __restrict__ g2, const float* __restrict__ b2,
        const float* __restrict__ m2, const float* __restrict__ v2) {
    __shared__ __align__(16) float As[16][64];
    __shared__ __align__(16) float Bs[16][128];
    int p0 = blockIdx.x * 128;
    int co0 = blockIdx.y * 64;
    int tid = threadIdx.x;
    int tx = tid & 31, ty = tid >> 5;
    float acc[8][4] = {};
    for (int k0 = 0; k0 < 768; k0 += 16) {
        #pragma unroll
        for (int i = 0; i < 4; i++) {
            int e = tid + i * 256;
            int kk = e >> 6, cc = e & 63;
            As[kk][cc] = g_weffT[(size_t)(k0 + kk) * C + co0 + cc];
        }
        #pragma unroll
        for (int i = 0; i < 8; i++) {
            int e = tid + i * 256;
            int kk = e >> 7, pp = e & 127;
            int k = k0 + kk;
            Bs[kk][pp] = (k < C) ? x[(size_t)k * HW + p0 + pp]
                                 : g_x2[(size_t)(k - C) * HW + p0 + pp];
        }
        __syncthreads();
        #pragma unroll
        for (int kk = 0; kk < 16; kk++) {
            float4 a0 = *(const float4*)&As[kk][ty * 8];
            float4 a1 = *(const float4*)&As[kk][ty * 8 + 4];
            float4 bb = *(const float4*)&Bs[kk][tx * 4];
            float av[8] = {a0.x, a0.y, a0.z, a0.w, a1.x, a1.y, a1.z, a1.w};
            float bv[4] = {bb.x, bb.y, bb.z, bb.w};
            #pragma unroll
            for (int i = 0; i < 8; i++)
                #pragma unroll
                for (int j = 0; j < 4; j++)
                    acc[i][j] += av[i] * bv[j];
        }
        __syncthreads();
    }
    #pragma unroll
    for (int i = 0; i < 8; i++) {
        int co = co0 + ty * 8 + i;
        float s = g2[co] * rsqrtf(v2[co] + EPS);
        float t0 = (bdc1[co] - m2[co]) * s + b2[co];
        float* op = g_h + (size_t)co * HW + p0 + tx * 4;
        #pragma unroll
        for (int j = 0; j < 4; j++) op[j] = acc[i][j] * s + t0;
    }
}

// ---------------- kernel 7: 3x3 conv 512->512 + bias + relu ----------------
__global__ __launch_bounds__(256, 2) void conv3_kernel(
        const float* __restrict__ bdc2, float* __restrict__ out) {
    __shared__ __align__(16) float s_in[8][10][34];
    __shared__ __align__(16) float s_w[8][9][64];
    int x0 = blockIdx.x * 32;
    int y0 = blockIdx.y * 8;
    int co0 = blockIdx.z * 64;
    int tid = threadIdx.x;
    int pg = tid & 31, cg = tid >> 5;
    float acc[8][8] = {};   // [co_u][row_r]
    for (int ci0 = 0; ci0 < C; ci0 += 8) {
        // load 8 input channels with halo (10x34)
        for (int e = tid; e < 8 * 340; e += 256) {
            int ci = e / 340;
            int rem = e - ci * 340;
            int yy = rem / 34, xx = rem - yy * 34;
            int gy = y0 - 1 + yy, gx = x0 - 1 + xx;
            float v = 0.f;
            if (gy >= 0 && gy < HH && gx >= 0 && gx < WW)
                v = g_h[(size_t)(ci0 + ci) * HW + gy * WW + gx];
            s_in[ci][yy][xx] = v;
        }
        // load weights [ci][tap][co]
        for (int e = tid; e < 8 * 9 * 64; e += 256) {
            int ci = e / 576;
            int rem = e - ci * 576;
            int tp = rem >> 6, cc = rem & 63;
            s_w[ci][tp][cc] = g_w2t[(size_t)((ci0 + ci) * 9 + tp) * C + co0 + cc];
        }
        __syncthreads();
        #pragma unroll
        for (int ci = 0; ci < 8; ci++) {
            #pragma unroll
            for (int dy = 0; dy < 3; dy++) {
                #pragma unroll
                for (int dx = 0; dx < 3; dx++) {
                    float bv[8];
                    #pragma unroll
                    for (int r = 0; r < 8; r++) bv[r] = s_in[ci][r + dy][pg + dx];
                    float4 w0 = *(const float4*)&s_w[ci][dy * 3 + dx][cg * 8];
                    float4 w1 = *(const float4*)&s_w[ci][dy * 3 + dx][cg * 8 + 4];
                    float wv[8] = {w0.x, w0.y, w0.z, w0.w, w1.x, w1.y, w1.z, w1.w};
                    #pragma unroll
                    for (int u = 0; u < 8; u++)
                        #pragma unroll
                        for (int r = 0; r < 8; r++)
                            acc[u][r] += wv[u] * bv[r];
                }
            }
        }
        __syncthreads();
    }
    #pragma unroll
    for (int u = 0; u < 8; u++) {
        int co = co0 + cg * 8 + u;
        float bb = bdc2[co];
        #pragma unroll
        for (int r = 0; r < 8; r++) {
            out[(size_t)co * HW + (y0 + r) * WW + x0 + pg] = fmaxf(acc[u][r] + bb, 0.f);
        }
    }
}

// ---------------- launch ----------------
extern "C" void kernel_launch(void* const* d_in, const int* in_sizes, int n_in,
                              void* d_out, int out_size) {
    (void)in_sizes; (void)n_in; (void)out_size;
    const float* x      = (const float*)d_in[0];
    const float* w_fc1  = (const float*)d_in[1];
    const float* w_fc2  = (const float*)d_in[2];
    const float* w_cheap= (const float*)d_in[3];
    const float* bn1_g  = (const float*)d_in[4];
    const float* bn1_b  = (const float*)d_in[5];
    const float* bn1_m  = (const float*)d_in[6];
    const float* bn1_v  = (const float*)d_in[7];
    const float* w_dc1  = (const float*)d_in[8];
    const float* b_dc1  = (const float*)d_in[9];
    const float* bn2_g  = (const float*)d_in[10];
    const float* bn2_b  = (const float*)d_in[11];
    const float* bn2_m  = (const float*)d_in[12];
    const float* bn2_v  = (const float*)d_in[13];
    const float* w_dc2  = (const float*)d_in[14];
    const float* b_dc2  = (const float*)d_in[15];
    float* out = (float*)d_out;

    reduce_kernel<<<C, 256>>>(x);
    mlp_select_kernel<<<1, 512>>>(w_fc1, w_fc2);
    weff_kernel<<<(768 * C + 255) / 256, 256>>>(w_dc1);
    w2t_kernel<<<(C * 9 * C + 255) / 256, 256>>>(w_dc2);
    x2_kernel<<<dim3(KSEL, 25), 256>>>(x, w_cheap, bn1_g, bn1_b, bn1_m, bn1_v);
    gemm_h_kernel<<<dim3(200, 8), 256>>>(x, b_dc1, bn2_g, bn2_b, bn2_m, bn2_v);
    conv3_kernel<<<dim3(5, 20, 8), 256>>>(b_dc2, out);
}

// round 3
// speedup vs baseline: 1.0037x; 1.0037x over previous
#include <cuda_runtime.h>
#include <math.h>

#define C 512
#define KSEL 256
#define HW 25600
#define HH 160
#define WW 160
#define EPS 1e-5f

// ---------------- device scratch ----------------
__device__ float g_avg[C];
__device__ float g_max[C];
__device__ float g_scales[C];
__device__ int   g_idx[KSEL];
__device__ int   g_pos[C];
__device__ float g_weffT[768 * C];        // [k][co], k in 0..767
__device__ float g_w2t[C * 9 * C];        // [(ci*9+t)][co]
__device__ float g_x2[KSEL * HW];         // depthwise output
__device__ float g_h[C * HW];             // after 1x1 conv + bn2

// ---------------- kernel 1: per-channel avg + max ----------------
__global__ void reduce_kernel(const float* __restrict__ x) {
    int c = blockIdx.x;
    const float* xc = x + (size_t)c * HW;
    float s = 0.f, m = -1e30f;
    for (int i = threadIdx.x; i < HW; i += blockDim.x) {
        float v = xc[i];
        s += v;
        m = fmaxf(m, v);
    }
    for (int o = 16; o > 0; o >>= 1) {
        s += __shfl_xor_sync(0xffffffffu, s, o);
        m = fmaxf(m, __shfl_xor_sync(0xffffffffu, m, o));
    }
    __shared__ float ws[8], wm[8];
    int wid = threadIdx.x >> 5;
    if ((threadIdx.x & 31) == 0) { ws[wid] = s; wm[wid] = m; }
    __syncthreads();
    if (threadIdx.x == 0) {
        float st = 0.f, mt = -1e30f;
        for (int i = 0; i < 8; i++) { st += ws[i]; mt = fmaxf(mt, wm[i]); }
        g_avg[c] = st / 25600.f;
        g_max[c] = mt;
    }
}

// ---------------- kernel 2: MLP + sigmoid + top-K selection ----------------
__global__ void mlp_select_kernel(const float* __restrict__ wfc1,
                                  const float* __restrict__ wfc2) {
    __shared__ float s_avg[C], s_max[C], s_hid[C], s_sc[C];
    __shared__ int s_sel[C];
    int t = threadIdx.x;
    s_avg[t] = g_avg[t];
    s_max[t] = g_max[t];
    __syncthreads();
    // hidden layers: threads 0..255 -> hid(avg), 256..511 -> hid(max)
    {
        const float* src = (t < 256) ? s_avg : s_max;
        int k = t & 255;
        const float* wr = wfc1 + (size_t)k * C;
        float acc = 0.f;
        #pragma unroll 8
        for (int c = 0; c < C; c++) acc += src[c] * wr[c];
        s_hid[t] = fmaxf(acc, 0.f);
    }
    __syncthreads();
    float acc = 0.f;
    {
        const float* wr = wfc2 + (size_t)t * 256;
        #pragma unroll 8
        for (int k = 0; k < 256; k++) acc += (s_hid[k] + s_hid[256 + k]) * wr[k];
    }
    float sc = 1.f / (1.f + expf(-acc));
    s_sc[t] = sc;
    g_scales[t] = sc;
    __syncthreads();
    // rank = number of elements that beat me (tie -> lower index wins)
    int rank = 0;
    for (int j = 0; j < C; j++) {
        float sj = s_sc[j];
        rank += (sj > sc) || (sj == sc && j < t);
    }
    int sel = (rank < KSEL) ? 1 : 0;
    s_sel[t] = sel;
    __syncthreads();
    int pos = 0;
    for (int j = 0; j < t; j++) pos += s_sel[j];
    if (sel) { g_idx[pos] = t; g_pos[t] = pos; }
    else      g_pos[t] = -1;
}

// ---------------- kernel 3: build effective 1x1 weights (transposed [k][co]) ----------------
__global__ void weff_kernel(const float* __restrict__ w_dc1) {
    int e = blockIdx.x * blockDim.x + threadIdx.x;   // 768*512
    if (e >= 768 * C) return;
    int k = e >> 9;
    int co = e & 511;
    float v;
    if (k < C) {
        v = g_scales[k] * w_dc1[(size_t)co * 1024 + k];
        int p = g_pos[k];
        if (p >= 0) v += w_dc1[(size_t)co * 1024 + 512 + p];
    } else {
        v = w_dc1[(size_t)co * 1024 + 768 + (k - C)];
    }
    g_weffT[(size_t)k * C + co] = v;
}

// ---------------- kernel 4: transpose w_dc2 -> [(ci*9+t)][co] ----------------
__global__ void w2t_kernel(const float* __restrict__ w_dc2) {
    int e = blockIdx.x * blockDim.x + threadIdx.x;   // 512*9*512
    if (e >= C * 9 * C) return;
    int co = e & 511;
    int kt = e >> 9;
    int ci = kt / 9;
    int tp = kt - ci * 9;
    g_w2t[e] = w_dc2[(size_t)co * (C * 9) + ci * 9 + tp];
}

// ---------------- kernel 5: depthwise 3x3 + bn1 + relu on selected channels ----------------
__global__ void x2_kernel(const float* __restrict__ x,
                          const float* __restrict__ wch,
                          const float* __restrict__ g1, const float* __restrict__ b1,
                          const float* __restrict__ m1, const float* __restrict__ v1) {
    int j = blockIdx.x;
    int ch = g_idx[j];
    float s = g1[j] * rsqrtf(v1[j] + EPS);
    float sh = b1[j] - m1[j] * s;
    float w[9];
    #pragma unroll
    for (int t = 0; t < 9; t++) w[t] = wch[j * 9 + t];
    const float* xc = x + (size_t)ch * HW;
    float* oc = g_x2 + (size_t)j * HW;
    int pbase = blockIdx.y * 1024;
    for (int p = pbase + threadIdx.x; p < pbase + 1024; p += 256) {
        int y = p / WW, xx = p - y * WW;
        float acc = 0.f;
        #pragma unroll
        for (int dy = 0; dy < 3; dy++) {
            int gy = y + dy - 1;
            if (gy < 0 || gy >= HH) continue;
            #pragma unroll
            for (int dx = 0; dx < 3; dx++) {
                int gx = xx + dx - 1;
                if (gx < 0 || gx >= WW) continue;
                acc += xc[gy * WW + gx] * w[dy * 3 + dx];
            }
        }
        oc[p] = fmaxf(acc * s + sh, 0.f);
    }
}

// ---------------- kernel 6: fused concat-1x1-conv GEMM (M=512, N=25600, K=768) + bn2 ----------------
__global__ __launch_bounds__(256) void gemm_h_kernel(
        const float* __restrict__ x,
        const float* __restrict__ bdc1,
        const float* __restrict__ g2, const float* __restrict__ b2,
        const float* __restrict__ m2, const float* __restrict__ v2) {
    __shared__ __align__(16) float As[16][64];
    __shared__ __align__(16) float Bs[16][128];
    int p0 = blockIdx.x * 128;
    int co0 = blockIdx.y * 64;
    int tid = threadIdx.x;
    int tx = tid & 31, ty = tid >> 5;
    float acc[8][4] = {};
    for (int k0 = 0; k0 < 768; k0 += 16) {
        #pragma unroll
        for (int i = 0; i < 4; i++) {
            int e = tid + i * 256;
            int kk = e >> 6, cc = e & 63;
            As[kk][cc] = g_weffT[(size_t)(k0 + kk) * C + co0 + cc];
        }
        #pragma unroll
        for (int i = 0; i < 8; i++) {
            int e = tid + i * 256;
            int kk = e >> 7, pp = e & 127;
            int k = k0 + kk;
            Bs[kk][pp] = (k < C) ? x[(size_t)k * HW + p0 + pp]
                                 : g_x2[(size_t)(k - C) * HW + p0 + pp];
        }
        __syncthreads();
        #pragma unroll
        for (int kk = 0; kk < 16; kk++) {
            float4 a0 = *(const float4*)&As[kk][ty * 8];
            float4 a1 = *(const float4*)&As[kk][ty * 8 + 4];
            float4 bb = *(const float4*)&Bs[kk][tx * 4];
            float av[8] = {a0.x, a0.y, a0.z, a0.w, a1.x, a1.y, a1.z, a1.w};
            float bv[4] = {bb.x, bb.y, bb.z, bb.w};
            #pragma unroll
            for (int i = 0; i < 8; i++)
                #pragma unroll
                for (int j = 0; j < 4; j++)
                    acc[i][j] += av[i] * bv[j];
        }
        __syncthreads();
    }
    #pragma unroll
    for (int i = 0; i < 8; i++) {
        int co = co0 + ty * 8 + i;
        float s = g2[co] * rsqrtf(v2[co] + EPS);
        float t0 = (bdc1[co] - m2[co]) * s + b2[co];
        float* op = g_h + (size_t)co * HW + p0 + tx * 4;
        #pragma unroll
        for (int j = 0; j < 4; j++) op[j] = acc[i][j] * s + t0;
    }
}

// ---------------- kernel 7: 3x3 conv 512->512 + bias + relu ----------------
__global__ __launch_bounds__(256, 2) void conv3_kernel(
        const float* __restrict__ bdc2, float* __restrict__ out) {
    __shared__ __align__(16) float s_in[8][10][34];
    __shared__ __align__(16) float s_w[8][9][64];
    int x0 = blockIdx.x * 32;
    int y0 = blockIdx.y * 8;
    int co0 = blockIdx.z * 64;
    int tid = threadIdx.x;
    int pg = tid & 31, cg = tid >> 5;
    float acc[8][8] = {};   // [co_u][row_r]
    for (int ci0 = 0; ci0 < C; ci0 += 8) {
        // load 8 input channels with halo (10x34)
        for (int e = tid; e < 8 * 340; e += 256) {
            int ci = e / 340;
            int rem = e - ci * 340;
            int yy = rem / 34, xx = rem - yy * 34;
            int gy = y0 - 1 + yy, gx = x0 - 1 + xx;
            float v = 0.f;
            if (gy >= 0 && gy < HH && gx >= 0 && gx < WW)
                v = g_h[(size_t)(ci0 + ci) * HW + gy * WW + gx];
            s_in[ci][yy][xx] = v;
        }
        // load weights [ci][tap][co]
        for (int e = tid; e < 8 * 9 * 64; e += 256) {
            int ci = e / 576;
            int rem = e - ci * 576;
            int tp = rem >> 6, cc = rem & 63;
            s_w[ci][tp][cc] = g_w2t[(size_t)((ci0 + ci) * 9 + tp) * C + co0 + cc];
        }
        __syncthreads();
        #pragma unroll
        for (int ci = 0; ci < 8; ci++) {
            #pragma unroll
            for (int dy = 0; dy < 3; dy++) {
                #pragma unroll
                for (int dx = 0; dx < 3; dx++) {
                    float bv[8];
                    #pragma unroll
                    for (int r = 0; r < 8; r++) bv[r] = s_in[ci][r + dy][pg + dx];
                    float4 w0 = *(const float4*)&s_w[ci][dy * 3 + dx][cg * 8];
                    float4 w1 = *(const float4*)&s_w[ci][dy * 3 + dx][cg * 8 + 4];
                    float wv[8] = {w0.x, w0.y, w0.z, w0.w, w1.x, w1.y, w1.z, w1.w};
                    #pragma unroll
                    for (int u = 0; u < 8; u++)
                        #pragma unroll
                        for (int r = 0; r < 8; r++)
                            acc[u][r] += wv[u] * bv[r];
                }
            }
        }
        __syncthreads();
    }
    #pragma unroll
    for (int u = 0; u < 8; u++) {
        int co = co0 + cg * 8 + u;
        float bb = bdc2[co];
        #pragma unroll
        for (int r = 0; r < 8; r++) {
            out[(size_t)co * HW + (y0 + r) * WW + x0 + pg] = fmaxf(acc[u][r] + bb, 0.f);
        }
    }
}

// ---------------- launch ----------------
extern "C" void kernel_launch(void* const* d_in, const int* in_sizes, int n_in,
                              void* d_out, int out_size) {
    (void)in_sizes; (void)n_in; (void)out_size;
    const float* x      = (const float*)d_in[0];
    const float* w_fc1  = (const float*)d_in[1];
    const float* w_fc2  = (const float*)d_in[2];
    const float* w_cheap= (const float*)d_in[3];
    const float* bn1_g  = (const float*)d_in[4];
    const float* bn1_b  = (const float*)d_in[5];
    const float* bn1_m  = (const float*)d_in[6];
    const float* bn1_v  = (const float*)d_in[7];
    const float* w_dc1  = (const float*)d_in[8];
    const float* b_dc1  = (const float*)d_in[9];
    const float* bn2_g  = (const float*)d_in[10];
    const float* bn2_b  = (const float*)d_in[11];
    const float* bn2_m  = (const float*)d_in[12];
    const float* bn2_v  = (const float*)d_in[13];
    const float* w_dc2  = (const float*)d_in[14];
    const float* b_dc2  = (const float*)d_in[15];
    float* out = (float*)d_out;

    reduce_kernel<<<C, 256>>>(x);
    mlp_select_kernel<<<1, 512>>>(w_fc1, w_fc2);
    weff_kernel<<<(768 * C + 255) / 256, 256>>>(w_dc1);
    w2t_kernel<<<(C * 9 * C + 255) / 256, 256>>>(w_dc2);
    x2_kernel<<<dim3(KSEL, 25), 256>>>(x, w_cheap, bn1_g, bn1_b, bn1_m, bn1_v);
    gemm_h_kernel<<<dim3(200, 8), 256>>>(x, b_dc1, bn2_g, bn2_b, bn2_m, bn2_v);
    conv3_kernel<<<dim3(5, 20, 8), 256>>>(b_dc2, out);
}

// round 11
// speedup vs baseline: 2.8513x; 2.8407x over previous
#include <cuda_runtime.h>
#include <math.h>
#include <stdint.h>

#define C 512
#define KSEL 256
#define HW 25600
#define HH 160
#define WW 160
#define PW 162
#define EPS 1e-5f
#define NCH1 24
#define NCH3 144
#define STRIDE 36                       // floats per smem row (conflict-free)
#define TILE_F (128 * STRIDE)           // floats per tile
#define DYN_SMEM (4 * TILE_F * 4)       // A0,A1,B0,B1 = 73728 B

// ---------------- device scratch ----------------
__device__ float g_avg[C], g_maxv[C], g_scales[C];
__device__ int   g_idx[KSEL], g_pos[C];
__device__ float g_weff[C * 768];                 // [co][k], tf32-rounded
__device__ float g_w2r[(size_t)NCH3 * C * 32];    // [chunk][co][32ci], tf32-rounded
__device__ float g_x2[(size_t)KSEL * HW];         // depthwise out
__device__ float g_xT[(size_t)HW * 768];          // [px][k], tf32-rounded
__device__ float g_hpad[(size_t)PW * PW * C];     // NHWC zero-padded (border stays 0)
__device__ float g_s2[C], g_t2[C];

// ---------------- helpers ----------------
__device__ __forceinline__ uint32_t s2u(const void* p) {
    uint32_t a;
    asm("{ .reg .u64 t; cvta.to.shared.u64 t, %1; cvt.u32.u64 %0, t; }" : "=r"(a) : "l"(p));
    return a;
}
__device__ __forceinline__ float rna(float v) {
    uint32_t o;
    asm("cvt.rna.tf32.f32 %0, %1;" : "=r"(o) : "f"(v));
    return __uint_as_float(o);
}
__device__ __forceinline__ void cp16(uint32_t d, const void* s) {
    asm volatile("cp.async.cg.shared.global [%0], [%1], 16;" :: "r"(d), "l"(s));
}
#define CP_COMMIT() asm volatile("cp.async.commit_group;" ::: "memory")
#define CP_WAIT1()  asm volatile("cp.async.wait_group 1;" ::: "memory")
#define CP_WAIT0()  asm volatile("cp.async.wait_group 0;" ::: "memory")

__device__ __forceinline__ void mma_tf32(float* c, const uint32_t* a, const uint32_t* b) {
    asm volatile(
        "mma.sync.aligned.m16n8k8.row.col.f32.tf32.tf32.f32 "
        "{%0,%1,%2,%3}, {%4,%5,%6,%7}, {%8,%9}, {%0,%1,%2,%3};"
        : "+f"(c[0]), "+f"(c[1]), "+f"(c[2]), "+f"(c[3])
        : "r"(a[0]), "r"(a[1]), "r"(a[2]), "r"(a[3]), "r"(b[0]), "r"(b[1]));
}

// warp computes 64x32 of the block tile from one 32-deep k-chunk
__device__ __forceinline__ void warp_mma_chunk(const float* __restrict__ sA,
                                               const float* __restrict__ sB,
                                               int mbase, int nbase, int g, int q,
                                               float c[4][4][4]) {
    #pragma unroll
    for (int k8 = 0; k8 < 4; k8++) {
        int kc = k8 * 8 + q;
        uint32_t a[4][4], b[4][2];
        #pragma unroll
        for (int mt = 0; mt < 4; mt++) {
            int r0 = mbase + mt * 16 + g;
            a[mt][0] = __float_as_uint(sA[r0 * STRIDE + kc]);
            a[mt][1] = __float_as_uint(sA[(r0 + 8) * STRIDE + kc]);
            a[mt][2] = __float_as_uint(sA[r0 * STRIDE + kc + 4]);
            a[mt][3] = __float_as_uint(sA[(r0 + 8) * STRIDE + kc + 4]);
        }
        #pragma unroll
        for (int nt = 0; nt < 4; nt++) {
            int n0 = nbase + nt * 8 + g;
            b[nt][0] = __float_as_uint(sB[n0 * STRIDE + k8 * 8 + q]);
            b[nt][1] = __float_as_uint(sB[n0 * STRIDE + k8 * 8 + q + 4]);
        }
        #pragma unroll
        for (int mt = 0; mt < 4; mt++)
            #pragma unroll
            for (int nt = 0; nt < 4; nt++)
                mma_tf32(c[mt][nt], a[mt], b[nt]);
    }
}

// ---------------- kernel 1: per-channel avg + max ----------------
__global__ void reduce_kernel(const float* __restrict__ x) {
    int c = blockIdx.x;
    const float* xc = x + (size_t)c * HW;
    float s = 0.f, m = -1e30f;
    for (int i = threadIdx.x; i < HW; i += blockDim.x) {
        float v = xc[i];
        s += v; m = fmaxf(m, v);
    }
    for (int o = 16; o > 0; o >>= 1) {
        s += __shfl_xor_sync(0xffffffffu, s, o);
        m = fmaxf(m, __shfl_xor_sync(0xffffffffu, m, o));
    }
    __shared__ float ws[8], wm[8];
    int wid = threadIdx.x >> 5;
    if ((threadIdx.x & 31) == 0) { ws[wid] = s; wm[wid] = m; }
    __syncthreads();
    if (threadIdx.x == 0) {
        float st = 0.f, mt = -1e30f;
        for (int i = 0; i < 8; i++) { st += ws[i]; mt = fmaxf(mt, wm[i]); }
        g_avg[c] = st / 25600.f;
        g_maxv[c] = mt;
    }
}

// ---------------- kernel 2: MLP + sigmoid + top-K selection ----------------
__global__ void mlp_select_kernel(const float* __restrict__ wfc1,
                                  const float* __restrict__ wfc2) {
    __shared__ float s_avg[C], s_max[C], s_hid[C], s_sc[C];
    __shared__ int s_sel[C];
    int t = threadIdx.x;
    s_avg[t] = g_avg[t];
    s_max[t] = g_maxv[t];
    __syncthreads();
    {
        const float* src = (t < 256) ? s_avg : s_max;
        int k = t & 255;
        const float* wr = wfc1 + (size_t)k * C;
        float acc = 0.f;
        #pragma unroll 8
        for (int c = 0; c < C; c++) acc += src[c] * wr[c];
        s_hid[t] = fmaxf(acc, 0.f);
    }
    __syncthreads();
    float acc = 0.f;
    {
        const float* wr = wfc2 + (size_t)t * 256;
        #pragma unroll 8
        for (int k = 0; k < 256; k++) acc += (s_hid[k] + s_hid[256 + k]) * wr[k];
    }
    float sc = 1.f / (1.f + expf(-acc));
    s_sc[t] = sc;
    g_scales[t] = sc;
    __syncthreads();
    int rank = 0;
    for (int j = 0; j < C; j++) {
        float sj = s_sc[j];
        rank += (sj > sc) || (sj == sc && j < t);
    }
    int sel = (rank < KSEL) ? 1 : 0;
    s_sel[t] = sel;
    __syncthreads();
    int pos = 0;
    for (int j = 0; j < t; j++) pos += s_sel[j];
    if (sel) { g_idx[pos] = t; g_pos[t] = pos; }
    else      g_pos[t] = -1;
}

// ---------------- kernel 3: bn2 fold ----------------
__global__ void bnfold_kernel(const float* __restrict__ bdc1,
                              const float* __restrict__ g2, const float* __restrict__ b2,
                              const float* __restrict__ m2, const float* __restrict__ v2) {
    int c = threadIdx.x;
    float s = g2[c] * rsqrtf(v2[c] + EPS);
    g_s2[c] = s;
    g_t2[c] = (bdc1[c] - m2[c]) * s + b2[c];
}

// ---------------- kernel 4: effective 1x1 weights [co][768] ----------------
__global__ void weff_kernel(const float* __restrict__ w_dc1) {
    int e = blockIdx.x * blockDim.x + threadIdx.x;
    if (e >= C * 768) return;
    int co = e / 768;
    int k  = e - co * 768;
    float v;
    if (k < C) {
        v = g_scales[k] * w_dc1[(size_t)co * 1024 + k];
        int p = g_pos[k];
        if (p >= 0) v += w_dc1[(size_t)co * 1024 + 512 + p];
    } else {
        v = w_dc1[(size_t)co * 1024 + 768 + (k - C)];
    }
    g_weff[e] = rna(v);
}

// ---------------- kernel 5: reorder w_dc2 -> [chunk][co][32] ----------------
__global__ void w2r_kernel(const float* __restrict__ w_dc2) {
    int e = blockIdx.x * 256 + threadIdx.x;
    if (e >= NCH3 * C * 32) return;
    int j  = e & 31;
    int co = (e >> 5) & 511;
    int ch = e >> 14;
    int tap = ch >> 4, cc = ch & 15;
    int ci = cc * 32 + j;
    g_w2r[e] = rna(w_dc2[(size_t)co * 4608 + ci * 9 + tap]);
}

// ---------------- kernel 6: depthwise 3x3 + bn1 + relu ----------------
__global__ void x2_kernel(const float* __restrict__ x,
                          const float* __restrict__ wch,
                          const float* __restrict__ g1, const float* __restrict__ b1,
                          const float* __restrict__ m1, const float* __restrict__ v1) {
    int j = blockIdx.x;
    int ch = g_idx[j];
    float s = g1[j] * rsqrtf(v1[j] + EPS);
    float sh = b1[j] - m1[j] * s;
    float w[9];
    #pragma unroll
    for (int t = 0; t < 9; t++) w[t] = wch[j * 9 + t];
    const float* xc = x + (size_t)ch * HW;
    float* oc = g_x2 + (size_t)j * HW;
    int pbase = blockIdx.y * 1024;
    for (int p = pbase + threadIdx.x; p < pbase + 1024; p += 256) {
        int y = p / WW, xx = p - y * WW;
        float acc = 0.f;
        #pragma unroll
        for (int dy = 0; dy < 3; dy++) {
            int gy = y + dy - 1;
            if (gy < 0 || gy >= HH) continue;
            #pragma unroll
            for (int dx = 0; dx < 3; dx++) {
                int gx = xx + dx - 1;
                if (gx < 0 || gx >= WW) continue;
                acc += xc[gy * WW + gx] * w[dy * 3 + dx];
            }
        }
        oc[p] = fmaxf(acc * s + sh, 0.f);
    }
}

// ---------------- kernel 7: transpose [k][p] -> xT[p][k] ----------------
__global__ void xT_kernel(const float* __restrict__ x) {
    __shared__ float t[32][33];
    int k0 = blockIdx.y * 32, p0 = blockIdx.x * 32;
    int lx = threadIdx.x & 31, ly = threadIdx.x >> 5;
    #pragma unroll
    for (int i = 0; i < 4; i++) {
        int k = k0 + ly + 8 * i;
        const float* src = (k < C) ? (x + (size_t)k * HW) : (g_x2 + (size_t)(k - C) * HW);
        t[ly + 8 * i][lx] = src[p0 + lx];
    }
    __syncthreads();
    #pragma unroll
    for (int i = 0; i < 4; i++) {
        int p = p0 + ly + 8 * i;
        g_xT[(size_t)p * 768 + k0 + lx] = rna(t[lx][ly + 8 * i]);
    }
}

// ---------------- kernel 8: 1x1 conv (tf32 mma.sync) + bn2 -> hpad NHWC ----------------
__global__ __launch_bounds__(256, 2) void gemm1_kernel() {
    extern __shared__ float dsm[];
    float* tiles[4] = {dsm, dsm + TILE_F, dsm + 2 * TILE_F, dsm + 3 * TILE_F};
    __shared__ float s_s2[128], s_t2[128];
    int tid = threadIdx.x, lane = tid & 31, wid = tid >> 5;
    int g = lane >> 2, q = lane & 3;
    int p0 = blockIdx.x << 7, co0 = blockIdx.y << 7;
    int mbase = (wid >> 2) * 64, nbase = (wid & 3) * 32;

    for (int i = tid; i < 128; i += 256) {
        s_s2[i] = g_s2[co0 + i];
        s_t2[i] = g_t2[co0 + i];
    }

    int r = tid >> 3, sf = (tid & 7) << 2;
    uint32_t sd[4];
    const float* gA[4];
    const float* gB[4];
    #pragma unroll
    for (int i = 0; i < 4; i++) {
        sd[i] = ((r + 32 * i) * STRIDE + sf) * 4;           // byte offset in tile
        gA[i] = g_xT   + (size_t)(p0  + r + 32 * i) * 768 + sf;
        gB[i] = g_weff + (size_t)(co0 + r + 32 * i) * 768 + sf;
    }
    uint32_t tb[4] = {s2u(tiles[0]), s2u(tiles[1]), s2u(tiles[2]), s2u(tiles[3])};

    float c[4][4][4] = {};

    // preload chunk 0 -> stage 0
    #pragma unroll
    for (int i = 0; i < 4; i++) { cp16(tb[0] + sd[i], gA[i]); cp16(tb[2] + sd[i], gB[i]); }
    CP_COMMIT();

    for (int it = 0; it < NCH1; it++) {
        int s = it & 1;
        if (it + 1 < NCH1) {
            int k0 = (it + 1) << 5;
            #pragma unroll
            for (int i = 0; i < 4; i++) {
                cp16(tb[s ^ 1] + sd[i], gA[i] + k0);
                cp16(tb[2 + (s ^ 1)] + sd[i], gB[i] + k0);
            }
            CP_COMMIT();
            CP_WAIT1();
        } else {
            CP_WAIT0();
        }
        __syncthreads();
        warp_mma_chunk(tiles[s], tiles[2 + s], mbase, nbase, g, q, c);
        __syncthreads();
    }

    // epilogue: bn2 + tf32 round -> hpad NHWC
    #pragma unroll
    for (int mt = 0; mt < 4; mt++) {
        #pragma unroll
        for (int h = 0; h < 2; h++) {
            int p = p0 + mbase + mt * 16 + g + 8 * h;
            int y = p / 160, xx = p - y * 160;
            float* orow = g_hpad + ((size_t)(y + 1) * PW + (xx + 1)) * C + co0;
            #pragma unroll
            for (int nt = 0; nt < 4; nt++) {
                int l = nbase + nt * 8 + q * 2;
                float v0 = c[mt][nt][2 * h]     * s_s2[l]     + s_t2[l];
                float v1 = c[mt][nt][2 * h + 1] * s_s2[l + 1] + s_t2[l + 1];
                float2 w; w.x = rna(v0); w.y = rna(v1);
                *(float2*)(orow + l) = w;
            }
        }
    }
}

// ---------------- kernel 9: 3x3 conv (tf32 mma.sync) + bias + relu -> out NCHW ----------------
__global__ __launch_bounds__(256, 2) void conv3_mma_kernel(const float* __restrict__ bias,
                                                           float* __restrict__ out) {
    extern __shared__ float dsm[];
    float* tiles[4] = {dsm, dsm + TILE_F, dsm + 2 * TILE_F, dsm + 3 * TILE_F};
    __shared__ float s_b[128];
    int tid = threadIdx.x, lane = tid & 31, wid = tid >> 5;
    int g = lane >> 2, q = lane & 3;
    int p0 = blockIdx.x << 7, co0 = blockIdx.y << 7;
    int mbase = (wid >> 2) * 64, nbase = (wid & 3) * 32;

    for (int i = tid; i < 128; i += 256) s_b[i] = bias[co0 + i];

    int r = tid >> 3, sf = (tid & 7) << 2;
    uint32_t sd[4];
    size_t apix[4];
    const float* gB[4];
    #pragma unroll
    for (int i = 0; i < 4; i++) {
        sd[i] = ((r + 32 * i) * STRIDE + sf) * 4;
        int p = p0 + r + 32 * i;
        int y = p / 160, xx = p - y * 160;
        apix[i] = ((size_t)y * PW + xx) * C + sf;
        gB[i] = g_w2r + (size_t)(co0 + r + 32 * i) * 32 + sf;
    }
    uint32_t tb[4] = {s2u(tiles[0]), s2u(tiles[1]), s2u(tiles[2]), s2u(tiles[3])};

    float c[4][4][4] = {};

    // chunk loader
    auto load_chunk = [&](int ch, int s) {
        int tap = ch >> 4;
        int dyq = tap / 3, dxq = tap - dyq * 3;
        size_t toff = ((size_t)dyq * PW + dxq) * C + ((size_t)(ch & 15) << 5);
        const float* bsrc = gB[0] + ((size_t)ch << 14);
        #pragma unroll
        for (int i = 0; i < 4; i++) {
            cp16(tb[s] + sd[i], g_hpad + apix[i] + toff);
            cp16(tb[2 + s] + sd[i], gB[i] + ((size_t)ch << 14));
        }
        (void)bsrc;
        CP_COMMIT();
    };

    load_chunk(0, 0);

    for (int it = 0; it < NCH3; it++) {
        int s = it & 1;
        if (it + 1 < NCH3) {
            load_chunk(it + 1, s ^ 1);
            CP_WAIT1();
        } else {
            CP_WAIT0();
        }
        __syncthreads();
        warp_mma_chunk(tiles[s], tiles[2 + s], mbase, nbase, g, q, c);
        __syncthreads();
    }

    // epilogue: bias + relu -> out[co][px]
    #pragma unroll
    for (int mt = 0; mt < 4; mt++) {
        #pragma unroll
        for (int h = 0; h < 2; h++) {
            int p = p0 + mbase + mt * 16 + g + 8 * h;
            #pragma unroll
            for (int nt = 0; nt < 4; nt++) {
                int l = nbase + nt * 8 + q * 2;
                int co = co0 + l;
                float v0 = c[mt][nt][2 * h]     + s_b[l];
                float v1 = c[mt][nt][2 * h + 1] + s_b[l + 1];
                out[(size_t)co * HW + p]       = fmaxf(v0, 0.f);
                out[(size_t)(co + 1) * HW + p] = fmaxf(v1, 0.f);
            }
        }
    }
}

// ---------------- launch ----------------
extern "C" void kernel_launch(void* const* d_in, const int* in_sizes, int n_in,
                              void* d_out, int out_size) {
    (void)in_sizes; (void)n_in; (void)out_size;
    const float* x      = (const float*)d_in[0];
    const float* w_fc1  = (const float*)d_in[1];
    const float* w_fc2  = (const float*)d_in[2];
    const float* w_cheap= (const float*)d_in[3];
    const float* bn1_g  = (const float*)d_in[4];
    const float* bn1_b  = (const float*)d_in[5];
    const float* bn1_m  = (const float*)d_in[6];
    const float* bn1_v  = (const float*)d_in[7];
    const float* w_dc1  = (const float*)d_in[8];
    const float* b_dc1  = (const float*)d_in[9];
    const float* bn2_g  = (const float*)d_in[10];
    const float* bn2_b  = (const float*)d_in[11];
    const float* bn2_m  = (const float*)d_in[12];
    const float* bn2_v  = (const float*)d_in[13];
    const float* w_dc2  = (const float*)d_in[14];
    const float* b_dc2  = (const float*)d_in[15];
    float* out = (float*)d_out;

    static int cfg_done = 0;
    if (!cfg_done) {
        cudaFuncSetAttribute(gemm1_kernel, cudaFuncAttributeMaxDynamicSharedMemorySize, DYN_SMEM);
        cudaFuncSetAttribute(conv3_mma_kernel, cudaFuncAttributeMaxDynamicSharedMemorySize, DYN_SMEM);
        cfg_done = 1;
    }

    reduce_kernel<<<C, 256>>>(x);
    mlp_select_kernel<<<1, 512>>>(w_fc1, w_fc2);
    bnfold_kernel<<<1, 512>>>(b_dc1, bn2_g, bn2_b, bn2_m, bn2_v);
    weff_kernel<<<(C * 768 + 255) / 256, 256>>>(w_dc1);
    w2r_kernel<<<(NCH3 * C * 32) / 256, 256>>>(w_dc2);
    x2_kernel<<<dim3(KSEL, 25), 256>>>(x, w_cheap, bn1_g, bn1_b, bn1_m, bn1_v);
    xT_kernel<<<dim3(800, 24), 256>>>(x);
    gemm1_kernel<<<dim3(200, 4), 256, DYN_SMEM>>>();
    conv3_mma_kernel<<<dim3(200, 4), 256, DYN_SMEM>>>(b_dc2, out);
}